// round 11
// baseline (speedup 1.0000x reference)
#include <cuda_runtime.h>
#include <cuda_bf16.h>
#include <cstdint>
#include <cstddef>

#define BB 4096
#define TT 64
#define II 60
#define HH 60
#define R3 180
#define CC 600
#define KFC 7680      // T * 2H
#define CPAD 640      // padded FC output rows (160 * 4)

// ---------------- device scratch ----------------
static __device__ __nv_bfloat16 g_hs_hi[(size_t)BB * KFC];   // 63 MB
static __device__ __nv_bfloat16 g_hs_lo[(size_t)BB * KFC];   // 63 MB
static __device__ __nv_bfloat16 g_w_hi[(size_t)CPAD * KFC];  // 9.8 MB
static __device__ __nv_bfloat16 g_w_lo[(size_t)CPAD * KFC];  // 9.8 MB

// ---------------- helpers (generic ISA only) ----------------
__device__ __forceinline__ unsigned long long ffma2(unsigned long long a,
                                                    unsigned long long b,
                                                    unsigned long long c) {
    unsigned long long d;
    asm("fma.rn.f32x2 %0, %1, %2, %3;" : "=l"(d) : "l"(a), "l"(b), "l"(c));
    return d;
}
__device__ __forceinline__ float hsum2(unsigned long long v) {
    return __uint_as_float((unsigned)v) + __uint_as_float((unsigned)(v >> 32));
}
__device__ __forceinline__ void cp16(void* sdst, const void* gsrc) {
    unsigned sa = (unsigned)__cvta_generic_to_shared(sdst);
    asm volatile("cp.async.cg.shared.global [%0], [%1], 16;" :: "r"(sa), "l"(gsrc));
}
__device__ __forceinline__ void ldsm_x4(uint32_t addr, uint32_t* r) {
    asm volatile("ldmatrix.sync.aligned.m8n8.x4.shared.b16 {%0,%1,%2,%3}, [%4];"
                 : "=r"(r[0]), "=r"(r[1]), "=r"(r[2]), "=r"(r[3]) : "r"(addr));
}
__device__ __forceinline__ void ldsm_x2(uint32_t addr, uint32_t* r) {
    asm volatile("ldmatrix.sync.aligned.m8n8.x2.shared.b16 {%0,%1}, [%2];"
                 : "=r"(r[0]), "=r"(r[1]) : "r"(addr));
}
__device__ __forceinline__ void mma16816(float* c, const uint32_t* a, const uint32_t* b) {
    asm volatile("mma.sync.aligned.m16n8k16.row.col.f32.bf16.bf16.f32 "
                 "{%0,%1,%2,%3}, {%4,%5,%6,%7}, {%8,%9}, {%0,%1,%2,%3};"
                 : "+f"(c[0]), "+f"(c[1]), "+f"(c[2]), "+f"(c[3])
                 : "r"(a[0]), "r"(a[1]), "r"(a[2]), "r"(a[3]),
                   "r"(b[0]), "r"(b[1]));
}

// =====================================================================
// Fused bidirectional GRU (FFMA2). grid (64, 2), block 512.
// Combine stage stores hidden states as hi/lo bf16 pair for the MMA FC.
// =====================================================================
#define GRU_THREADS 512

#define OFF_WIH   0
#define OFF_WHH   13056
#define OFF_X     26112
#define OFF_H     34816
#define OFF_GH    39168
#define OFF_GXN   51712
#define OFF_BRZ   56064
#define OFF_BIN   56184
#define OFF_BHN   56244
#define GRU_SMEM_FLOATS 56304

__global__ void __launch_bounds__(GRU_THREADS, 1) gru_fused(
    const float* __restrict__ x,
    const float* __restrict__ w_ih, const float* __restrict__ w_hh,
    const float* __restrict__ b_ih, const float* __restrict__ b_hh)
{
    extern __shared__ float sm[];
    float* wih_s = sm + OFF_WIH;
    float* whh_s = sm + OFF_WHH;
    float* x_s   = sm + OFF_X;
    float* h_s   = sm + OFF_H;
    float* gh_s  = sm + OFF_GH;
    float* gxn_s = sm + OFF_GXN;
    float* brz_s = sm + OFF_BRZ;
    float* bin_s = sm + OFF_BIN;
    float* bhn_s = sm + OFF_BHN;

    const int tid = threadIdx.x;
    const int tx  = tid & 15;
    const int ty  = tid >> 4;
    const int d   = blockIdx.y;
    const int b0  = blockIdx.x * 64;

    for (int i = tid; i < 13056; i += GRU_THREADS) { wih_s[i] = 0.f; whh_s[i] = 0.f; }
    for (int i = tid; i < 8704;  i += GRU_THREADS) x_s[i] = 0.f;
    for (int i = tid; i < 4352;  i += GRU_THREADS) h_s[i] = 0.f;
    __syncthreads();

    const float* wih_g = w_ih + (size_t)d * R3 * II;
    const float* whh_g = w_hh + (size_t)d * R3 * HH;
    for (int idx = tid; idx < 180 * 16; idx += GRU_THREADS) {
        int r = idx >> 4, q = idx & 15;
        if (q < 15) {
            *(float4*)&wih_s[r * 68 + q * 4] = *(const float4*)&wih_g[r * 60 + q * 4];
            *(float4*)&whh_s[r * 68 + q * 4] = *(const float4*)&whh_g[r * 60 + q * 4];
        }
    }
    for (int j = tid; j < 120; j += GRU_THREADS)
        brz_s[j] = b_ih[d * R3 + j] + b_hh[d * R3 + j];
    for (int j = tid; j < 60; j += GRU_THREADS) {
        bin_s[j] = b_ih[d * R3 + 120 + j];
        bhn_s[j] = b_hh[d * R3 + 120 + j];
    }

    {
        const int t0 = (d == 0) ? 0 : (TT - 1);
#pragma unroll
        for (int p = 0; p < 2; p++) {
            int idx = tid + p * GRU_THREADS;
            int q = idx & 15, b = idx >> 4;
            if (q < 15)
                cp16(&x_s[b * 68 + q * 4],
                     &x[((size_t)(b0 + b) * TT + t0) * II + q * 4]);
        }
        asm volatile("cp.async.commit_group;");
    }
    __syncthreads();

    unsigned long long acc[6][4];

    for (int s = 0; s < TT; s++) {
        const int t   = (d == 0) ? s : (TT - 1 - s);
        const int cur = s & 1;
        const int nxt = cur ^ 1;

        if (s + 1 < TT) {
            const int tn = (d == 0) ? (s + 1) : (TT - 2 - s);
#pragma unroll
            for (int p = 0; p < 2; p++) {
                int idx = tid + p * GRU_THREADS;
                int q = idx & 15, b = idx >> 4;
                if (q < 15)
                    cp16(&x_s[nxt * 4352 + b * 68 + q * 4],
                         &x[((size_t)(b0 + b) * TT + tn) * II + q * 4]);
            }
        }
        asm volatile("cp.async.commit_group;");
        asm volatile("cp.async.wait_group 1;");
        __syncthreads();

#pragma unroll
        for (int i = 0; i < 6; i++)
#pragma unroll
            for (int j = 0; j < 4; j++) acc[i][j] = 0ull;

        const float* xb = &x_s[cur * 4352];
#pragma unroll 5
        for (int k4 = 0; k4 < 15; k4++) {
            ulonglong2 xv[4];
#pragma unroll
            for (int j = 0; j < 4; j++)
                xv[j] = *(const ulonglong2*)&xb[(tx + 16 * j) * 68 + k4 * 4];
#pragma unroll
            for (int i = 0; i < 6; i++) {
                ulonglong2 wv = *(const ulonglong2*)&wih_s[(ty + 32 * i) * 68 + k4 * 4];
#pragma unroll
                for (int j = 0; j < 4; j++) {
                    acc[i][j] = ffma2(wv.x, xv[j].x, acc[i][j]);
                    acc[i][j] = ffma2(wv.y, xv[j].y, acc[i][j]);
                }
            }
        }

#pragma unroll
        for (int i = 0; i < 6; i++) {
            const int r = ty + 32 * i;
            if (r >= 120 && r < 180) {
#pragma unroll
                for (int j = 0; j < 4; j++)
                    gxn_s[(tx + 16 * j) * 68 + (r - 120)] = hsum2(acc[i][j]);
            }
        }

#pragma unroll 5
        for (int k4 = 0; k4 < 15; k4++) {
            ulonglong2 xv[4];
#pragma unroll
            for (int j = 0; j < 4; j++)
                xv[j] = *(const ulonglong2*)&h_s[(tx + 16 * j) * 68 + k4 * 4];
#pragma unroll
            for (int i = 0; i < 6; i++) {
                ulonglong2 wv = *(const ulonglong2*)&whh_s[(ty + 32 * i) * 68 + k4 * 4];
#pragma unroll
                for (int j = 0; j < 4; j++) {
                    acc[i][j] = ffma2(wv.x, xv[j].x, acc[i][j]);
                    acc[i][j] = ffma2(wv.y, xv[j].y, acc[i][j]);
                }
            }
        }

#pragma unroll
        for (int i = 0; i < 6; i++) {
            const int r = ty + 32 * i;
#pragma unroll
            for (int j = 0; j < 4; j++)
                gh_s[(tx + 16 * j) * 196 + r] = hsum2(acc[i][j]);
        }
        __syncthreads();

#pragma unroll
        for (int p = 0; p < 8; p++) {
            const int idx = tid + p * GRU_THREADS;
            const int b = idx >> 6, j = idx & 63;
            if (j < 60) {
                const float tr = gh_s[b * 196 + j]       + brz_s[j];
                const float tz = gh_s[b * 196 + 60 + j]  + brz_s[60 + j];
                const float tn = gh_s[b * 196 + 120 + j];
                const float xn = gxn_s[b * 68 + j];
                const float nx = xn + bin_s[j];
                const float nh = (tn - xn) + bhn_s[j];
                const float rg = 1.f / (1.f + __expf(-tr));
                const float zg = 1.f / (1.f + __expf(-tz));
                const float a  = fmaf(rg, nh, nx);
                const float ng = 1.f - 2.f / (__expf(2.f * a) + 1.f);
                const float ho = h_s[b * 68 + j];
                const float hn = fmaf(zg, ho - ng, ng);
                h_s[b * 68 + j] = hn;
                const size_t o = ((size_t)(b0 + b) * TT + t) * 120 + d * 60 + j;
                const __nv_bfloat16 hi = __float2bfloat16(hn);
                g_hs_hi[o] = hi;
                g_hs_lo[o] = __float2bfloat16(hn - __bfloat162float(hi));
            }
        }
        __syncthreads();
    }
}

// =====================================================================
// fc_w -> hi/lo bf16 split, rows padded to 640 with zeros.
// =====================================================================
__global__ void __launch_bounds__(256) wconv_kernel(const float* __restrict__ fcw)
{
    const size_t e = ((size_t)blockIdx.x * 256 + threadIdx.x) * 4;
    if (e >= (size_t)CPAD * KFC) return;
    const int r = (int)(e / KFC);
    const int k = (int)(e % KFC);
    float4 v = make_float4(0.f, 0.f, 0.f, 0.f);
    if (r < CC) v = *(const float4*)&fcw[(size_t)r * KFC + k];
    __nv_bfloat16 hi[4], lo[4];
    const float vv[4] = {v.x, v.y, v.z, v.w};
#pragma unroll
    for (int i = 0; i < 4; i++) {
        hi[i] = __float2bfloat16(vv[i]);
        lo[i] = __float2bfloat16(vv[i] - __bfloat162float(hi[i]));
    }
    *(uint2*)&g_w_hi[e] = *(const uint2*)hi;
    *(uint2*)&g_w_lo[e] = *(const uint2*)lo;
}

// =====================================================================
// FC via mma.sync bf16 (generic ISA). out = hs @ W^T + b, hi/lo x3.
// CTA tile 128x160, grid (32, 4) = 128 CTAs (one wave), 256 threads.
// Warp tile 64x40 (4 m-frags x 5 n-frags of m16n8k16). K-tile 32,
// 3-stage cp.async pipeline, smem row stride 80 B (ldmatrix conflict-free).
// =====================================================================
#define FCM 128
#define FCN 160
#define FCK 32
#define NK2 (KFC / FCK)              // 240
#define A_ST 10240                   // 128 * 80
#define B_ST 12800                   // 160 * 80
#define STG_BYTES (2 * A_ST + 2 * B_ST)   // 46080
#define F_AHI 0
#define F_ALO A_ST
#define F_BHI (2 * A_ST)
#define F_BLO (2 * A_ST + B_ST)
#define FC_SMEM (3 * STG_BYTES)      // 138240

__device__ __forceinline__ void fc_load(char* smem, int s, int m0, int c0,
                                        int k0, int tid)
{
    char* stg = smem + s * STG_BYTES;
#pragma unroll
    for (int p = 0; p < 9; p++) {
        const int cid = tid + p * 256;
        if (cid < 512) {                       // A hi: 128 rows x 4 chunks
            const int r = cid >> 2, q = cid & 3;
            cp16(stg + F_AHI + r * 80 + q * 16,
                 &g_hs_hi[(size_t)(m0 + r) * KFC + k0 + q * 8]);
        } else if (cid < 1024) {               // A lo
            const int c2 = cid - 512, r = c2 >> 2, q = c2 & 3;
            cp16(stg + F_ALO + r * 80 + q * 16,
                 &g_hs_lo[(size_t)(m0 + r) * KFC + k0 + q * 8]);
        } else if (cid < 1664) {               // B hi: 160 rows x 4 chunks
            const int c2 = cid - 1024, r = c2 >> 2, q = c2 & 3;
            cp16(stg + F_BHI + r * 80 + q * 16,
                 &g_w_hi[(size_t)(c0 + r) * KFC + k0 + q * 8]);
        } else {                               // B lo
            const int c2 = cid - 1664, r = c2 >> 2, q = c2 & 3;
            cp16(stg + F_BLO + r * 80 + q * 16,
                 &g_w_lo[(size_t)(c0 + r) * KFC + k0 + q * 8]);
        }
    }
}

__global__ void __launch_bounds__(256, 1) fc_mma(const float* __restrict__ fcb,
                                                 float* __restrict__ out)
{
    extern __shared__ __align__(128) char smem[];

    const int tid    = threadIdx.x;
    const int wid    = tid >> 5;
    const int lane   = tid & 31;
    const int warp_m = wid >> 2;     // 0..1
    const int warp_n = wid & 3;      // 0..3
    const int m0     = blockIdx.x * FCM;
    const int c0     = blockIdx.y * FCN;

    const uint32_t sbase = (uint32_t)__cvta_generic_to_shared(smem);

    // ldmatrix per-lane address components
    const int a_row = warp_m * 64 + (lane & 15);   // + mt*16
    const int a_kb  = (lane >> 4) * 16;            // k-halves within 32B
    const int b_row = warp_n * 40 + (lane & 7);    // + nt*8
    const int b_kb  = ((lane >> 3) & 1) * 16;

    float acc[4][5][4];
#pragma unroll
    for (int i = 0; i < 4; i++)
#pragma unroll
        for (int j = 0; j < 5; j++)
#pragma unroll
            for (int q = 0; q < 4; q++) acc[i][j][q] = 0.f;

    // prologue: fill 3 stages
#pragma unroll
    for (int p = 0; p < 3; p++) {
        fc_load(smem, p, m0, c0, p * FCK, tid);
        asm volatile("cp.async.commit_group;");
    }

    for (int kt = 0; kt < NK2; kt++) {
        const int s = kt % 3;
        asm volatile("cp.async.wait_group 2;");
        __syncthreads();

        const uint32_t sa = sbase + s * STG_BYTES;
#pragma unroll
        for (int kk = 0; kk < 2; kk++) {
            const uint32_t kb = kk * 32;
            uint32_t Ah[4][4], Bh[5][2], Bl[5][2], Al[4][4];
#pragma unroll
            for (int mt = 0; mt < 4; mt++)
                ldsm_x4(sa + F_AHI + (uint32_t)(a_row + mt * 16) * 80 + kb + a_kb,
                        Ah[mt]);
#pragma unroll
            for (int nt = 0; nt < 5; nt++)
                ldsm_x2(sa + F_BHI + (uint32_t)(b_row + nt * 8) * 80 + kb + b_kb,
                        Bh[nt]);
#pragma unroll
            for (int mt = 0; mt < 4; mt++)
#pragma unroll
                for (int nt = 0; nt < 5; nt++)
                    mma16816(acc[mt][nt], Ah[mt], Bh[nt]);

#pragma unroll
            for (int nt = 0; nt < 5; nt++)
                ldsm_x2(sa + F_BLO + (uint32_t)(b_row + nt * 8) * 80 + kb + b_kb,
                        Bl[nt]);
#pragma unroll
            for (int mt = 0; mt < 4; mt++)
#pragma unroll
                for (int nt = 0; nt < 5; nt++)
                    mma16816(acc[mt][nt], Ah[mt], Bl[nt]);

#pragma unroll
            for (int mt = 0; mt < 4; mt++)
                ldsm_x4(sa + F_ALO + (uint32_t)(a_row + mt * 16) * 80 + kb + a_kb,
                        Al[mt]);
#pragma unroll
            for (int mt = 0; mt < 4; mt++)
#pragma unroll
                for (int nt = 0; nt < 5; nt++)
                    mma16816(acc[mt][nt], Al[mt], Bh[nt]);
        }
        __syncthreads();

        if (kt + 3 < NK2)
            fc_load(smem, s, m0, c0, (kt + 3) * FCK, tid);
        asm volatile("cp.async.commit_group;");   // empty group ok -> constant accounting
    }

    // epilogue: acc -> out with bias
#pragma unroll
    for (int mt = 0; mt < 4; mt++) {
        const int row = m0 + warp_m * 64 + mt * 16 + (lane >> 2);
#pragma unroll
        for (int nt = 0; nt < 5; nt++) {
            const int col = c0 + warp_n * 40 + nt * 8 + 2 * (lane & 3);
            if (col < CC) {
                const float b0v = __ldg(&fcb[col]);
                const float b1v = __ldg(&fcb[col + 1]);
                float2 v0 = make_float2(acc[mt][nt][0] + b0v, acc[mt][nt][1] + b1v);
                float2 v1 = make_float2(acc[mt][nt][2] + b0v, acc[mt][nt][3] + b1v);
                *(float2*)&out[(size_t)row * CC + col] = v0;
                *(float2*)&out[(size_t)(row + 8) * CC + col] = v1;
            }
        }
    }
}

// =====================================================================
extern "C" void kernel_launch(void* const* d_in, const int* in_sizes, int n_in,
                              void* d_out, int out_size)
{
    (void)in_sizes; (void)n_in; (void)out_size;
    const float* x    = (const float*)d_in[0];
    const float* w_ih = (const float*)d_in[1];
    const float* w_hh = (const float*)d_in[2];
    const float* b_ih = (const float*)d_in[3];
    const float* b_hh = (const float*)d_in[4];
    const float* fc_w = (const float*)d_in[5];
    const float* fc_b = (const float*)d_in[6];
    float* out = (float*)d_out;

    cudaFuncSetAttribute(gru_fused, cudaFuncAttributeMaxDynamicSharedMemorySize,
                         GRU_SMEM_FLOATS * 4);
    cudaFuncSetAttribute(fc_mma, cudaFuncAttributeMaxDynamicSharedMemorySize,
                         FC_SMEM);

    wconv_kernel<<<((size_t)CPAD * KFC / 4 + 255) / 256, 256>>>(fc_w);

    gru_fused<<<dim3(64, 2), GRU_THREADS, GRU_SMEM_FLOATS * 4>>>(
        x, w_ih, w_hh, b_ih, b_hh);

    fc_mma<<<dim3(BB / FCM, CPAD / FCN), 256, FC_SMEM>>>(fc_b, out);
}

// round 12
// speedup vs baseline: 1.0027x; 1.0027x over previous
#include <cuda_runtime.h>
#include <cuda_bf16.h>
#include <cstdint>
#include <cstddef>

#define BB 4096
#define TT 64
#define II 60
#define HH 60
#define R3 180
#define CC 600
#define KFC 7680      // T * 2H
#define CPAD 640      // padded FC output rows (160 * 4)

// ---------------- device scratch ----------------
static __device__ __nv_bfloat16 g_hs_hi[(size_t)BB * KFC];   // 63 MB
static __device__ __nv_bfloat16 g_hs_lo[(size_t)BB * KFC];   // 63 MB
static __device__ __nv_bfloat16 g_w_hi[(size_t)CPAD * KFC];  // 9.8 MB
static __device__ __nv_bfloat16 g_w_lo[(size_t)CPAD * KFC];  // 9.8 MB

// ---------------- helpers (generic ISA only) ----------------
__device__ __forceinline__ unsigned long long ffma2(unsigned long long a,
                                                    unsigned long long b,
                                                    unsigned long long c) {
    unsigned long long d;
    asm("fma.rn.f32x2 %0, %1, %2, %3;" : "=l"(d) : "l"(a), "l"(b), "l"(c));
    return d;
}
__device__ __forceinline__ float hsum2(unsigned long long v) {
    return __uint_as_float((unsigned)v) + __uint_as_float((unsigned)(v >> 32));
}
__device__ __forceinline__ void cp16(void* sdst, const void* gsrc) {
    unsigned sa = (unsigned)__cvta_generic_to_shared(sdst);
    asm volatile("cp.async.cg.shared.global [%0], [%1], 16;" :: "r"(sa), "l"(gsrc));
}
__device__ __forceinline__ void ldsm_x4(uint32_t addr, uint32_t* r) {
    asm volatile("ldmatrix.sync.aligned.m8n8.x4.shared.b16 {%0,%1,%2,%3}, [%4];"
                 : "=r"(r[0]), "=r"(r[1]), "=r"(r[2]), "=r"(r[3]) : "r"(addr));
}
__device__ __forceinline__ void ldsm_x2(uint32_t addr, uint32_t* r) {
    asm volatile("ldmatrix.sync.aligned.m8n8.x2.shared.b16 {%0,%1}, [%2];"
                 : "=r"(r[0]), "=r"(r[1]) : "r"(addr));
}
__device__ __forceinline__ void mma16816(float* c, const uint32_t* a, const uint32_t* b) {
    asm volatile("mma.sync.aligned.m16n8k16.row.col.f32.bf16.bf16.f32 "
                 "{%0,%1,%2,%3}, {%4,%5,%6,%7}, {%8,%9}, {%0,%1,%2,%3};"
                 : "+f"(c[0]), "+f"(c[1]), "+f"(c[2]), "+f"(c[3])
                 : "r"(a[0]), "r"(a[1]), "r"(a[2]), "r"(a[3]),
                   "r"(b[0]), "r"(b[1]));
}

// =====================================================================
// Fused bidirectional GRU (FFMA2). grid (64, 2), block 512.
// Combine stage stores hidden states as hi/lo bf16 pair for the MMA FC.
// =====================================================================
#define GRU_THREADS 512

#define OFF_WIH   0
#define OFF_WHH   13056
#define OFF_X     26112
#define OFF_H     34816
#define OFF_GH    39168
#define OFF_GXN   51712
#define OFF_BRZ   56064
#define OFF_BIN   56184
#define OFF_BHN   56244
#define GRU_SMEM_FLOATS 56304

__global__ void __launch_bounds__(GRU_THREADS, 1) gru_fused(
    const float* __restrict__ x,
    const float* __restrict__ w_ih, const float* __restrict__ w_hh,
    const float* __restrict__ b_ih, const float* __restrict__ b_hh)
{
    extern __shared__ float sm[];
    float* wih_s = sm + OFF_WIH;
    float* whh_s = sm + OFF_WHH;
    float* x_s   = sm + OFF_X;
    float* h_s   = sm + OFF_H;
    float* gh_s  = sm + OFF_GH;
    float* gxn_s = sm + OFF_GXN;
    float* brz_s = sm + OFF_BRZ;
    float* bin_s = sm + OFF_BIN;
    float* bhn_s = sm + OFF_BHN;

    const int tid = threadIdx.x;
    const int tx  = tid & 15;
    const int ty  = tid >> 4;
    const int d   = blockIdx.y;
    const int b0  = blockIdx.x * 64;

    for (int i = tid; i < 13056; i += GRU_THREADS) { wih_s[i] = 0.f; whh_s[i] = 0.f; }
    for (int i = tid; i < 8704;  i += GRU_THREADS) x_s[i] = 0.f;
    for (int i = tid; i < 4352;  i += GRU_THREADS) h_s[i] = 0.f;
    __syncthreads();

    const float* wih_g = w_ih + (size_t)d * R3 * II;
    const float* whh_g = w_hh + (size_t)d * R3 * HH;
    for (int idx = tid; idx < 180 * 16; idx += GRU_THREADS) {
        int r = idx >> 4, q = idx & 15;
        if (q < 15) {
            *(float4*)&wih_s[r * 68 + q * 4] = *(const float4*)&wih_g[r * 60 + q * 4];
            *(float4*)&whh_s[r * 68 + q * 4] = *(const float4*)&whh_g[r * 60 + q * 4];
        }
    }
    for (int j = tid; j < 120; j += GRU_THREADS)
        brz_s[j] = b_ih[d * R3 + j] + b_hh[d * R3 + j];
    for (int j = tid; j < 60; j += GRU_THREADS) {
        bin_s[j] = b_ih[d * R3 + 120 + j];
        bhn_s[j] = b_hh[d * R3 + 120 + j];
    }

    {
        const int t0 = (d == 0) ? 0 : (TT - 1);
#pragma unroll
        for (int p = 0; p < 2; p++) {
            int idx = tid + p * GRU_THREADS;
            int q = idx & 15, b = idx >> 4;
            if (q < 15)
                cp16(&x_s[b * 68 + q * 4],
                     &x[((size_t)(b0 + b) * TT + t0) * II + q * 4]);
        }
        asm volatile("cp.async.commit_group;");
    }
    __syncthreads();

    unsigned long long acc[6][4];

    for (int s = 0; s < TT; s++) {
        const int t   = (d == 0) ? s : (TT - 1 - s);
        const int cur = s & 1;
        const int nxt = cur ^ 1;

        if (s + 1 < TT) {
            const int tn = (d == 0) ? (s + 1) : (TT - 2 - s);
#pragma unroll
            for (int p = 0; p < 2; p++) {
                int idx = tid + p * GRU_THREADS;
                int q = idx & 15, b = idx >> 4;
                if (q < 15)
                    cp16(&x_s[nxt * 4352 + b * 68 + q * 4],
                         &x[((size_t)(b0 + b) * TT + tn) * II + q * 4]);
            }
        }
        asm volatile("cp.async.commit_group;");
        asm volatile("cp.async.wait_group 1;");
        __syncthreads();

#pragma unroll
        for (int i = 0; i < 6; i++)
#pragma unroll
            for (int j = 0; j < 4; j++) acc[i][j] = 0ull;

        const float* xb = &x_s[cur * 4352];
#pragma unroll 5
        for (int k4 = 0; k4 < 15; k4++) {
            ulonglong2 xv[4];
#pragma unroll
            for (int j = 0; j < 4; j++)
                xv[j] = *(const ulonglong2*)&xb[(tx + 16 * j) * 68 + k4 * 4];
#pragma unroll
            for (int i = 0; i < 6; i++) {
                ulonglong2 wv = *(const ulonglong2*)&wih_s[(ty + 32 * i) * 68 + k4 * 4];
#pragma unroll
                for (int j = 0; j < 4; j++) {
                    acc[i][j] = ffma2(wv.x, xv[j].x, acc[i][j]);
                    acc[i][j] = ffma2(wv.y, xv[j].y, acc[i][j]);
                }
            }
        }

#pragma unroll
        for (int i = 0; i < 6; i++) {
            const int r = ty + 32 * i;
            if (r >= 120 && r < 180) {
#pragma unroll
                for (int j = 0; j < 4; j++)
                    gxn_s[(tx + 16 * j) * 68 + (r - 120)] = hsum2(acc[i][j]);
            }
        }

#pragma unroll 5
        for (int k4 = 0; k4 < 15; k4++) {
            ulonglong2 xv[4];
#pragma unroll
            for (int j = 0; j < 4; j++)
                xv[j] = *(const ulonglong2*)&h_s[(tx + 16 * j) * 68 + k4 * 4];
#pragma unroll
            for (int i = 0; i < 6; i++) {
                ulonglong2 wv = *(const ulonglong2*)&whh_s[(ty + 32 * i) * 68 + k4 * 4];
#pragma unroll
                for (int j = 0; j < 4; j++) {
                    acc[i][j] = ffma2(wv.x, xv[j].x, acc[i][j]);
                    acc[i][j] = ffma2(wv.y, xv[j].y, acc[i][j]);
                }
            }
        }

#pragma unroll
        for (int i = 0; i < 6; i++) {
            const int r = ty + 32 * i;
#pragma unroll
            for (int j = 0; j < 4; j++)
                gh_s[(tx + 16 * j) * 196 + r] = hsum2(acc[i][j]);
        }
        __syncthreads();

#pragma unroll
        for (int p = 0; p < 8; p++) {
            const int idx = tid + p * GRU_THREADS;
            const int b = idx >> 6, j = idx & 63;
            if (j < 60) {
                const float tr = gh_s[b * 196 + j]       + brz_s[j];
                const float tz = gh_s[b * 196 + 60 + j]  + brz_s[60 + j];
                const float tn = gh_s[b * 196 + 120 + j];
                const float xn = gxn_s[b * 68 + j];
                const float nx = xn + bin_s[j];
                const float nh = (tn - xn) + bhn_s[j];
                const float rg = 1.f / (1.f + __expf(-tr));
                const float zg = 1.f / (1.f + __expf(-tz));
                const float a  = fmaf(rg, nh, nx);
                const float ng = 1.f - 2.f / (__expf(2.f * a) + 1.f);
                const float ho = h_s[b * 68 + j];
                const float hn = fmaf(zg, ho - ng, ng);
                h_s[b * 68 + j] = hn;
                const size_t o = ((size_t)(b0 + b) * TT + t) * 120 + d * 60 + j;
                const __nv_bfloat16 hi = __float2bfloat16(hn);
                g_hs_hi[o] = hi;
                g_hs_lo[o] = __float2bfloat16(hn - __bfloat162float(hi));
            }
        }
        __syncthreads();
    }
}

// =====================================================================
// fc_w -> hi/lo bf16 split, rows padded to 640 with zeros.
// =====================================================================
__global__ void __launch_bounds__(256) wconv_kernel(const float* __restrict__ fcw)
{
    const size_t e = ((size_t)blockIdx.x * 256 + threadIdx.x) * 4;
    if (e >= (size_t)CPAD * KFC) return;
    const int r = (int)(e / KFC);
    const int k = (int)(e % KFC);
    float4 v = make_float4(0.f, 0.f, 0.f, 0.f);
    if (r < CC) v = *(const float4*)&fcw[(size_t)r * KFC + k];
    __nv_bfloat16 hi[4], lo[4];
    const float vv[4] = {v.x, v.y, v.z, v.w};
#pragma unroll
    for (int i = 0; i < 4; i++) {
        hi[i] = __float2bfloat16(vv[i]);
        lo[i] = __float2bfloat16(vv[i] - __bfloat162float(hi[i]));
    }
    *(uint2*)&g_w_hi[e] = *(const uint2*)hi;
    *(uint2*)&g_w_lo[e] = *(const uint2*)lo;
}

// =====================================================================
// FC via mma.sync bf16 (generic ISA). out = hs @ W^T + b, hi/lo x3.
// CTA tile 128x160, grid (32, 4) = 128 CTAs (one wave), 256 threads.
// Warp tile 64x40 (4 m-frags x 5 n-frags of m16n8k16). K-tile 32,
// 3-stage cp.async pipeline, smem row stride 80 B (ldmatrix conflict-free).
// =====================================================================
#define FCM 128
#define FCN 160
#define FCK 32
#define NK2 (KFC / FCK)              // 240
#define A_ST 10240                   // 128 * 80
#define B_ST 12800                   // 160 * 80
#define STG_BYTES (2 * A_ST + 2 * B_ST)   // 46080
#define F_AHI 0
#define F_ALO A_ST
#define F_BHI (2 * A_ST)
#define F_BLO (2 * A_ST + B_ST)
#define FC_SMEM (3 * STG_BYTES)      // 138240

__device__ __forceinline__ void fc_load(char* smem, int s, int m0, int c0,
                                        int k0, int tid)
{
    char* stg = smem + s * STG_BYTES;
#pragma unroll
    for (int p = 0; p < 9; p++) {
        const int cid = tid + p * 256;
        if (cid < 512) {                       // A hi: 128 rows x 4 chunks
            const int r = cid >> 2, q = cid & 3;
            cp16(stg + F_AHI + r * 80 + q * 16,
                 &g_hs_hi[(size_t)(m0 + r) * KFC + k0 + q * 8]);
        } else if (cid < 1024) {               // A lo
            const int c2 = cid - 512, r = c2 >> 2, q = c2 & 3;
            cp16(stg + F_ALO + r * 80 + q * 16,
                 &g_hs_lo[(size_t)(m0 + r) * KFC + k0 + q * 8]);
        } else if (cid < 1664) {               // B hi: 160 rows x 4 chunks
            const int c2 = cid - 1024, r = c2 >> 2, q = c2 & 3;
            cp16(stg + F_BHI + r * 80 + q * 16,
                 &g_w_hi[(size_t)(c0 + r) * KFC + k0 + q * 8]);
        } else {                               // B lo
            const int c2 = cid - 1664, r = c2 >> 2, q = c2 & 3;
            cp16(stg + F_BLO + r * 80 + q * 16,
                 &g_w_lo[(size_t)(c0 + r) * KFC + k0 + q * 8]);
        }
    }
}

__global__ void __launch_bounds__(256, 1) fc_mma(const float* __restrict__ fcb,
                                                 float* __restrict__ out)
{
    extern __shared__ __align__(128) char smem[];

    const int tid    = threadIdx.x;
    const int wid    = tid >> 5;
    const int lane   = tid & 31;
    const int warp_m = wid >> 2;     // 0..1
    const int warp_n = wid & 3;      // 0..3
    const int m0     = blockIdx.x * FCM;
    const int c0     = blockIdx.y * FCN;

    const uint32_t sbase = (uint32_t)__cvta_generic_to_shared(smem);

    // ldmatrix per-lane address components
    const int a_row = warp_m * 64 + (lane & 15);   // + mt*16
    const int a_kb  = (lane >> 4) * 16;            // k-halves within 32B
    const int b_row = warp_n * 40 + (lane & 7);    // + nt*8
    const int b_kb  = ((lane >> 3) & 1) * 16;

    float acc[4][5][4];
#pragma unroll
    for (int i = 0; i < 4; i++)
#pragma unroll
        for (int j = 0; j < 5; j++)
#pragma unroll
            for (int q = 0; q < 4; q++) acc[i][j][q] = 0.f;

    // prologue: fill 3 stages
#pragma unroll
    for (int p = 0; p < 3; p++) {
        fc_load(smem, p, m0, c0, p * FCK, tid);
        asm volatile("cp.async.commit_group;");
    }

    for (int kt = 0; kt < NK2; kt++) {
        const int s = kt % 3;
        asm volatile("cp.async.wait_group 2;");
        __syncthreads();

        const uint32_t sa = sbase + s * STG_BYTES;
#pragma unroll
        for (int kk = 0; kk < 2; kk++) {
            const uint32_t kb = kk * 32;
            uint32_t Ah[4][4], Bh[5][2], Bl[5][2], Al[4][4];
#pragma unroll
            for (int mt = 0; mt < 4; mt++)
                ldsm_x4(sa + F_AHI + (uint32_t)(a_row + mt * 16) * 80 + kb + a_kb,
                        Ah[mt]);
#pragma unroll
            for (int nt = 0; nt < 5; nt++)
                ldsm_x2(sa + F_BHI + (uint32_t)(b_row + nt * 8) * 80 + kb + b_kb,
                        Bh[nt]);
#pragma unroll
            for (int mt = 0; mt < 4; mt++)
#pragma unroll
                for (int nt = 0; nt < 5; nt++)
                    mma16816(acc[mt][nt], Ah[mt], Bh[nt]);

#pragma unroll
            for (int nt = 0; nt < 5; nt++)
                ldsm_x2(sa + F_BLO + (uint32_t)(b_row + nt * 8) * 80 + kb + b_kb,
                        Bl[nt]);
#pragma unroll
            for (int mt = 0; mt < 4; mt++)
#pragma unroll
                for (int nt = 0; nt < 5; nt++)
                    mma16816(acc[mt][nt], Ah[mt], Bl[nt]);

#pragma unroll
            for (int mt = 0; mt < 4; mt++)
                ldsm_x4(sa + F_ALO + (uint32_t)(a_row + mt * 16) * 80 + kb + a_kb,
                        Al[mt]);
#pragma unroll
            for (int mt = 0; mt < 4; mt++)
#pragma unroll
                for (int nt = 0; nt < 5; nt++)
                    mma16816(acc[mt][nt], Al[mt], Bh[nt]);
        }
        __syncthreads();

        if (kt + 3 < NK2)
            fc_load(smem, s, m0, c0, (kt + 3) * FCK, tid);
        asm volatile("cp.async.commit_group;");   // empty group ok -> constant accounting
    }

    // epilogue: acc -> out with bias
#pragma unroll
    for (int mt = 0; mt < 4; mt++) {
        const int row = m0 + warp_m * 64 + mt * 16 + (lane >> 2);
#pragma unroll
        for (int nt = 0; nt < 5; nt++) {
            const int col = c0 + warp_n * 40 + nt * 8 + 2 * (lane & 3);
            if (col < CC) {
                const float b0v = __ldg(&fcb[col]);
                const float b1v = __ldg(&fcb[col + 1]);
                float2 v0 = make_float2(acc[mt][nt][0] + b0v, acc[mt][nt][1] + b1v);
                float2 v1 = make_float2(acc[mt][nt][2] + b0v, acc[mt][nt][3] + b1v);
                *(float2*)&out[(size_t)row * CC + col] = v0;
                *(float2*)&out[(size_t)(row + 8) * CC + col] = v1;
            }
        }
    }
}

// =====================================================================
extern "C" void kernel_launch(void* const* d_in, const int* in_sizes, int n_in,
                              void* d_out, int out_size)
{
    (void)in_sizes; (void)n_in; (void)out_size;
    const float* x    = (const float*)d_in[0];
    const float* w_ih = (const float*)d_in[1];
    const float* w_hh = (const float*)d_in[2];
    const float* b_ih = (const float*)d_in[3];
    const float* b_hh = (const float*)d_in[4];
    const float* fc_w = (const float*)d_in[5];
    const float* fc_b = (const float*)d_in[6];
    float* out = (float*)d_out;

    cudaFuncSetAttribute(gru_fused, cudaFuncAttributeMaxDynamicSharedMemorySize,
                         GRU_SMEM_FLOATS * 4);
    cudaFuncSetAttribute(fc_mma, cudaFuncAttributeMaxDynamicSharedMemorySize,
                         FC_SMEM);

    wconv_kernel<<<((size_t)CPAD * KFC / 4 + 255) / 256, 256>>>(fc_w);

    gru_fused<<<dim3(64, 2), GRU_THREADS, GRU_SMEM_FLOATS * 4>>>(
        x, w_ih, w_hh, b_ih, b_hh);

    fc_mma<<<dim3(BB / FCM, CPAD / FCN), 256, FC_SMEM>>>(fc_b, out);
}